// round 9
// baseline (speedup 1.0000x reference)
#include <cuda_runtime.h>
#include <cstdint>

#define H 1024
#define SEQ 512
#define VOCAB 50257

#define FNB 592          // front kernel: 4 CTAs/SM x 148 SMs, all resident

// logits kernel: 8 warps/block, 2 rows/warp -> 16 rows/block
#define LROWS 16
#define NLOGB ((VOCAB + LROWS - 1) / LROWS)   // 3142

// output layout: [log_softmax(VOCAB) | h(H) | c(H) | attn_weights(SEQ)]
#define OUT_H  (VOCAB)
#define OUT_C  (VOCAB + H)
#define OUT_AW (VOCAB + 2 * H)

// ---------------- device scratch ----------------
__device__ float g_attn_logits[SEQ];
__device__ float g_attn_applied[H];
__device__ float g_x[H];
__device__ float g_h[H];
__device__ float g_gih[4 * H];   // x @ w_ih.T partials
__device__ float g_ghh[4 * H];   // h0 @ w_hh.T partials
__device__ float g_pmax[NLOGB];
__device__ float g_psum[NLOGB];
__device__ unsigned g_barcnt;    // monotonic grid-barrier counter (replay-safe)

__device__ __forceinline__ float dot4(float4 a, float4 b) {
    return a.x * b.x + a.y * b.y + a.z * b.z + a.w * b.w;
}

// Streaming v4 load via inline PTX: volatile ordering forces batched LDG.128.
__device__ __forceinline__ float4 ldcs4(const float4* p) {
    float4 v;
    asm volatile("ld.global.cs.v4.f32 {%0,%1,%2,%3}, [%4];"
                 : "=f"(v.x), "=f"(v.y), "=f"(v.z), "=f"(v.w) : "l"(p));
    return v;
}

// 1024-float dot: 8 batched LDG.128 per lane, FMAs against smem vector.
__device__ __forceinline__ float row_dot_1024(const float4* __restrict__ w,
                                              const float4* s, int lane) {
    float4 w0 = ldcs4(w + lane);
    float4 w1 = ldcs4(w + lane + 32);
    float4 w2 = ldcs4(w + lane + 64);
    float4 w3 = ldcs4(w + lane + 96);
    float4 w4 = ldcs4(w + lane + 128);
    float4 w5 = ldcs4(w + lane + 160);
    float4 w6 = ldcs4(w + lane + 192);
    float4 w7 = ldcs4(w + lane + 224);
    float acc = dot4(s[lane], w0);
    acc += dot4(s[lane + 32],  w1);
    acc += dot4(s[lane + 64],  w2);
    acc += dot4(s[lane + 96],  w3);
    acc += dot4(s[lane + 128], w4);
    acc += dot4(s[lane + 160], w5);
    acc += dot4(s[lane + 192], w6);
    acc += dot4(s[lane + 224], w7);
    return acc;
}

__device__ __forceinline__ float warp_sum(float v) {
#pragma unroll
    for (int o = 16; o > 0; o >>= 1) v += __shfl_down_sync(0xffffffffu, v, o);
    return v;
}

__device__ __forceinline__ float sigmoidf_(float x) {
    return 1.0f / (1.0f + expf(-x));
}

// Grid-wide barrier: monotonic counter (replay-safe). All FNB blocks are
// resident (launch_bounds(256,4) guarantees 4 CTAs/SM), so spinning is safe.
__device__ __forceinline__ void grid_sync() {
    __syncthreads();
    if (threadIdx.x == 0) {
        __threadfence();
        unsigned old = atomicAdd(&g_barcnt, 1u);
        unsigned target = (old / FNB + 1u) * FNB;
        while (*((volatile unsigned*)&g_barcnt) < target) { }
        __threadfence();
    }
    __syncthreads();
}

// ---- front kernel: everything before the vocab projection ----
__global__ void __launch_bounds__(256, 4) front_kernel(
    const int* __restrict__ idx,
    const float* __restrict__ h0,
    const float* __restrict__ c0,
    const float* __restrict__ enc,
    const float* __restrict__ emb,
    const float* __restrict__ attn_W,
    const float* __restrict__ attn_b,
    const float* __restrict__ comb_W,
    const float* __restrict__ comb_b,
    const float* __restrict__ w_ih,
    const float* __restrict__ w_hh,
    const float* __restrict__ b_ih,
    const float* __restrict__ b_hh,
    float* __restrict__ out)
{
    __shared__ float4 sin[512];      // 8KB staging
    __shared__ float  sred[256];
    __shared__ float  saw[8];
    __shared__ float  spart[8];

    const int t = threadIdx.x, warp = t >> 5, lane = t & 31;
    const int b = blockIdx.x;
    const int row = idx[0];
    const float4* e4  = (const float4*)(emb + (size_t)row * H);
    const float4* h04 = (const float4*)h0;

    // ===== P1: attn scores (blocks 0..63) | w_hh partials (64..575) | zero (576) =====
    if (b < 64) {
        sin[t]       = e4[t];
        sin[256 + t] = h04[t];
        __syncthreads();
        int r = b * 8 + warp;                    // 0..511
        const float4* w = (const float4*)(attn_W + (size_t)r * (2 * H));
        float acc = row_dot_1024(w, sin, lane)
                  + row_dot_1024(w + 256, sin + 256, lane);
        acc = warp_sum(acc);
        if (lane == 0) g_attn_logits[r] = acc + attn_b[r];
    } else if (b < 576) {
        sin[t] = h04[t];
        __syncthreads();
        int r = (b - 64) * 8 + warp;             // 0..4095 exactly
        const float4* w = (const float4*)(w_hh + (size_t)r * H);
        float acc = row_dot_1024(w, sin, lane);
        acc = warp_sum(acc);
        if (lane == 0) g_ghh[r] = acc;
    } else if (b == 576) {
        ((float4*)g_attn_applied)[t] = make_float4(0.f, 0.f, 0.f, 0.f);
    }
    grid_sync();

    // ===== P2: softmax (redundant per participating block) + attn_applied =====
    if (b < 64) {
        float v0 = g_attn_logits[t];
        float v1 = g_attn_logits[t + 256];
        sred[t] = fmaxf(v0, v1);
        __syncthreads();
        for (int k = 128; k > 0; k >>= 1) {
            if (t < k) sred[t] = fmaxf(sred[t], sred[t + k]);
            __syncthreads();
        }
        float m = sred[0];
        __syncthreads();
        float e0 = expf(v0 - m), e1 = expf(v1 - m);
        sred[t] = e0 + e1;
        __syncthreads();
        for (int k = 128; k > 0; k >>= 1) {
            if (t < k) sred[t] += sred[t + k];
            __syncthreads();
        }
        float inv = 1.0f / sred[0];
        if (b == 0) {
            out[OUT_AW + t] = e0 * inv;
            out[OUT_AW + t + 256] = e1 * inv;
        }
        int r0 = b * 8;
        if (t < 8) saw[t] = expf(g_attn_logits[r0 + t] - m) * inv;
        __syncthreads();
        const float4* enc4 = (const float4*)enc;
        float4 acc = make_float4(0.f, 0.f, 0.f, 0.f);
#pragma unroll
        for (int s = 0; s < 8; s++) {
            float w = saw[s];
            float4 v = ldcs4(&enc4[(size_t)(r0 + s) * 256 + t]);
            acc.x += w * v.x; acc.y += w * v.y; acc.z += w * v.z; acc.w += w * v.w;
        }
        atomicAdd(&g_attn_applied[4 * t + 0], acc.x);
        atomicAdd(&g_attn_applied[4 * t + 1], acc.y);
        atomicAdd(&g_attn_applied[4 * t + 2], acc.z);
        atomicAdd(&g_attn_applied[4 * t + 3], acc.w);
    }
    grid_sync();

    // ===== P3: comb (blocks 0..255, 2 warps/row split-K, 4 rows/block) =====
    if (b < 256) {
        sin[t]       = e4[t];
        sin[256 + t] = ((const float4*)g_attn_applied)[t];
        __syncthreads();
        int r    = b * 4 + (warp >> 1);          // 0..1023
        int half = warp & 1;
        const float4* w = (const float4*)(comb_W + (size_t)r * (2 * H)) + half * 256;
        float acc = row_dot_1024(w, sin + half * 256, lane);
        acc = warp_sum(acc);
        if (lane == 0) spart[warp] = acc;
        __syncthreads();
        if (t < 4) {
            int rr = b * 4 + t;
            g_x[rr] = fmaxf(spart[2 * t] + spart[2 * t + 1] + comb_b[rr], 0.0f);
        }
    }
    grid_sync();

    // ===== P4: w_ih partials (blocks 0..511, warp per row) =====
    if (b < 512) {
        sin[t] = ((const float4*)g_x)[t];
        __syncthreads();
        int r = b * 8 + warp;                    // 0..4095
        const float4* w = (const float4*)(w_ih + (size_t)r * H);
        float acc = row_dot_1024(w, sin, lane);
        acc = warp_sum(acc);
        if (lane == 0) g_gih[r] = acc;
    }
    grid_sync();

    // ===== P5: LSTM elementwise (blocks 0..3) =====
    if (b < 4) {
        int j = b * 256 + t;
        float gi = g_gih[j]         + g_ghh[j]         + b_ih[j]         + b_hh[j];
        float gf = g_gih[H + j]     + g_ghh[H + j]     + b_ih[H + j]     + b_hh[H + j];
        float gg = g_gih[2 * H + j] + g_ghh[2 * H + j] + b_ih[2 * H + j] + b_hh[2 * H + j];
        float go = g_gih[3 * H + j] + g_ghh[3 * H + j] + b_ih[3 * H + j] + b_hh[3 * H + j];
        float i_ = sigmoidf_(gi);
        float f_ = sigmoidf_(gf);
        float g_ = tanhf(gg);
        float o_ = sigmoidf_(go);
        float c = f_ * c0[j] + i_ * g_;
        float h = o_ * tanhf(c);
        g_h[j] = h;
        out[OUT_H + j] = h;
        out[OUT_C + j] = c;
    }
}

// ---- logits + fused block LSE: 2 rows per warp, inline loads ----
__global__ void __launch_bounds__(256) logits_kernel(
        const float* __restrict__ out_W, const float* __restrict__ out_b,
        float* __restrict__ out) {
    __shared__ float4 sh[256];
    __shared__ float s_m[8], s_s[8];
    int t = threadIdx.x, warp = t >> 5, lane = t & 31;
    sh[t] = ((const float4*)g_h)[t];
    __syncthreads();
    int r0 = blockIdx.x * LROWS + warp * 2;   // grid = NLOGB
    int r1 = r0 + 1;
    float m = -1e30f, s = 0.0f;
    if (r0 < VOCAB) {
        const float4* w0 = (const float4*)(out_W + (size_t)r0 * H);
        const float4* w1 = (const float4*)(out_W + (size_t)r1 * H);
        bool has1 = (r1 < VOCAB);
        float acc0 = 0.0f, acc1 = 0.0f;
#pragma unroll
        for (int k = 0; k < 8; k++) {
            int i = lane + 32 * k;
            float4 hv = sh[i];
            acc0 += dot4(hv, __ldcs(&w0[i]));
            if (has1) acc1 += dot4(hv, __ldcs(&w1[i]));
        }
        acc0 = warp_sum(acc0);
        acc1 = warp_sum(acc1);
        if (lane == 0) {
            float L0 = acc0 + out_b[r0];
            out[r0] = L0;
            m = L0; s = 1.0f;
            if (has1) {
                float L1 = acc1 + out_b[r1];
                out[r1] = L1;
                float M = fmaxf(m, L1);
                s = expf(m - M) + expf(L1 - M);
                m = M;
            }
        }
    }
    if (lane == 0) { s_m[warp] = m; s_s[warp] = s; }
    __syncthreads();
    if (t == 0) {
        float M = s_m[0], S = s_s[0];
#pragma unroll
        for (int k = 1; k < 8; k++) {
            float m2 = s_m[k], s2 = s_s[k];
            float Mx = fmaxf(M, m2);
            S = S * expf(M - Mx) + s2 * expf(m2 - Mx);
            M = Mx;
        }
        g_pmax[blockIdx.x] = M;
        g_psum[blockIdx.x] = S;
    }
}

// ---- final LSE combine (redundant per block) + subtract ----
__global__ void __launch_bounds__(256) sub_lse_kernel(float* __restrict__ out) {
    __shared__ float rm[256], rs[256];
    int t = threadIdx.x;
    float m = -1e30f, s = 0.0f;
    for (int i = t; i < NLOGB; i += 256) {
        float m2 = g_pmax[i], s2 = g_psum[i];
        float M = fmaxf(m, m2);
        s = s * expf(m - M) + s2 * expf(m2 - M);
        m = M;
    }
    rm[t] = m; rs[t] = s;
    __syncthreads();
    for (int k = 128; k > 0; k >>= 1) {
        if (t < k) {
            float m2 = rm[t + k], s2 = rs[t + k];
            float M = fmaxf(rm[t], m2);
            rs[t] = rs[t] * expf(rm[t] - M) + s2 * expf(m2 - M);
            rm[t] = M;
        }
        __syncthreads();
    }
    float lse = rm[0] + logf(rs[0]);
    int base = blockIdx.x * 1024;             // grid = 50
#pragma unroll
    for (int k = 0; k < 4; k++) {
        int i = base + t + 256 * k;
        if (i < VOCAB) out[i] -= lse;
    }
}

extern "C" void kernel_launch(void* const* d_in, const int* in_sizes, int n_in,
                              void* d_out, int out_size) {
    const int*   idx     = (const int*)  d_in[0];
    const float* h0      = (const float*)d_in[1];
    const float* c0      = (const float*)d_in[2];
    const float* enc     = (const float*)d_in[3];
    const float* emb     = (const float*)d_in[4];
    const float* attn_W  = (const float*)d_in[5];
    const float* attn_b  = (const float*)d_in[6];
    const float* comb_W  = (const float*)d_in[7];
    const float* comb_b  = (const float*)d_in[8];
    const float* w_ih    = (const float*)d_in[9];
    const float* w_hh    = (const float*)d_in[10];
    const float* b_ih    = (const float*)d_in[11];
    const float* b_hh    = (const float*)d_in[12];
    const float* out_W   = (const float*)d_in[13];
    const float* out_b   = (const float*)d_in[14];
    float* out = (float*)d_out;

    front_kernel<<<FNB, 256>>>(idx, h0, c0, enc, emb, attn_W, attn_b,
                               comb_W, comb_b, w_ih, w_hh, b_ih, b_hh, out);
    logits_kernel<<<NLOGB, 256>>>(out_W, out_b, out);
    sub_lse_kernel<<<(VOCAB + 1023) / 1024, 256>>>(out);
}

// round 10
// speedup vs baseline: 1.0160x; 1.0160x over previous
#include <cuda_runtime.h>
#include <cstdint>

#define H 1024
#define SEQ 512
#define VOCAB 50257

// logits kernel: 8 warps/block, 4 rows/warp -> 32 rows/block
#define LROWS 32
#define NLOGB ((VOCAB + LROWS - 1) / LROWS)   // 1571

// output layout: [log_softmax(VOCAB) | h(H) | c(H) | attn_weights(SEQ)]
#define OUT_H  (VOCAB)
#define OUT_C  (VOCAB + H)
#define OUT_AW (VOCAB + 2 * H)

// ---------------- device scratch ----------------
__device__ float g_attn_logits[SEQ];
__device__ float g_attn_applied[H];
__device__ float g_x[H];
__device__ float g_h[H];
__device__ float g_ghh[4 * H];   // h0 @ w_hh.T partials
__device__ float g_pmax[NLOGB];
__device__ float g_psum[NLOGB];

__device__ __forceinline__ float dot4(float4 a, float4 b) {
    return a.x * b.x + a.y * b.y + a.z * b.z + a.w * b.w;
}

// Streaming v4 load via inline PTX: volatile ordering forces batched LDG.128.
__device__ __forceinline__ float4 ldcs4(const float4* p) {
    float4 v;
    asm volatile("ld.global.cs.v4.f32 {%0,%1,%2,%3}, [%4];"
                 : "=f"(v.x), "=f"(v.y), "=f"(v.z), "=f"(v.w) : "l"(p));
    return v;
}

// 1024-float dot: 8 batched LDG.128 per lane, FMAs against smem vector.
__device__ __forceinline__ float row_dot_1024(const float4* __restrict__ w,
                                              const float4* s, int lane) {
    float4 w0 = ldcs4(w + lane);
    float4 w1 = ldcs4(w + lane + 32);
    float4 w2 = ldcs4(w + lane + 64);
    float4 w3 = ldcs4(w + lane + 96);
    float4 w4 = ldcs4(w + lane + 128);
    float4 w5 = ldcs4(w + lane + 160);
    float4 w6 = ldcs4(w + lane + 192);
    float4 w7 = ldcs4(w + lane + 224);
    float acc = dot4(s[lane], w0);
    acc += dot4(s[lane + 32],  w1);
    acc += dot4(s[lane + 64],  w2);
    acc += dot4(s[lane + 96],  w3);
    acc += dot4(s[lane + 128], w4);
    acc += dot4(s[lane + 160], w5);
    acc += dot4(s[lane + 192], w6);
    acc += dot4(s[lane + 224], w7);
    return acc;
}

__device__ __forceinline__ float warp_sum(float v) {
#pragma unroll
    for (int o = 16; o > 0; o >>= 1) v += __shfl_down_sync(0xffffffffu, v, o);
    return v;
}

__device__ __forceinline__ float sigmoidf_(float x) {
    return 1.0f / (1.0f + expf(-x));
}

// ---- 1. FUSED: attn scores (blocks 0..127, split-K) + w_hh partials (128..639) ----
__global__ void __launch_bounds__(256) attn_whh_kernel(
        const int* __restrict__ idx, const float* __restrict__ emb,
        const float* __restrict__ h0, const float* __restrict__ attn_W,
        const float* __restrict__ attn_b, const float* __restrict__ w_hh) {
    __shared__ float4 sin[512];
    __shared__ float spart[8];
    int t = threadIdx.x, warp = t >> 5, lane = t & 31;
    int b = blockIdx.x;
    if (b < 128) {
        int row = idx[0];
        sin[t]       = ((const float4*)(emb + (size_t)row * H))[t];
        sin[256 + t] = ((const float4*)h0)[t];
        __syncthreads();
        int r    = b * 4 + (warp >> 1);       // rows 0..511
        int half = warp & 1;
        const float4* w = (const float4*)(attn_W + (size_t)r * (2 * H)) + half * 256;
        float acc = row_dot_1024(w, sin + half * 256, lane);
        acc = warp_sum(acc);
        if (lane == 0) spart[warp] = acc;
        __syncthreads();
        if (t < 4) {
            int rr = b * 4 + t;
            g_attn_logits[rr] = spart[2 * t] + spart[2 * t + 1] + attn_b[rr];
        }
        // block 0 zeroes the attn_applied atomic accumulator (stream order
        // makes this race-free: next kernel is the only consumer/producer).
        if (b == 0) ((float4*)g_attn_applied)[t] = make_float4(0.f, 0.f, 0.f, 0.f);
    } else {
        sin[t] = ((const float4*)h0)[t];      // only first 256 entries used
        __syncthreads();
        int r = (b - 128) * 8 + warp;         // 512 blocks * 8 warps = 4096
        const float4* w = (const float4*)(w_hh + (size_t)r * H);
        float acc = row_dot_1024(w, sin, lane);
        acc = warp_sum(acc);
        if (lane == 0) g_ghh[r] = acc;
    }
}

// ---- 2. fused softmax (redundant per block) + attn_applied slice ----
__global__ void __launch_bounds__(256) attn_applied_kernel(
        const float* __restrict__ enc, float* __restrict__ out) {
    __shared__ float sred[256];
    __shared__ float saw[8];
    int t = threadIdx.x;
    float v0 = g_attn_logits[t];
    float v1 = g_attn_logits[t + 256];
    sred[t] = fmaxf(v0, v1);
    __syncthreads();
    for (int k = 128; k > 0; k >>= 1) {
        if (t < k) sred[t] = fmaxf(sred[t], sred[t + k]);
        __syncthreads();
    }
    float m = sred[0];
    __syncthreads();
    float e0 = expf(v0 - m), e1 = expf(v1 - m);
    sred[t] = e0 + e1;
    __syncthreads();
    for (int k = 128; k > 0; k >>= 1) {
        if (t < k) sred[t] += sred[t + k];
        __syncthreads();
    }
    float inv = 1.0f / sred[0];
    if (blockIdx.x == 0) {                    // one block persists the weights
        out[OUT_AW + t] = e0 * inv;
        out[OUT_AW + t + 256] = e1 * inv;
    }
    int r0 = blockIdx.x * 8;                  // grid = 64
    if (t < 8) saw[t] = expf(g_attn_logits[r0 + t] - m) * inv;
    __syncthreads();
    const float4* e4 = (const float4*)enc;
    float4 acc = make_float4(0.f, 0.f, 0.f, 0.f);
#pragma unroll
    for (int s = 0; s < 8; s++) {
        float w = saw[s];
        float4 v = ldcs4(&e4[(size_t)(r0 + s) * 256 + t]);
        acc.x += w * v.x; acc.y += w * v.y; acc.z += w * v.z; acc.w += w * v.w;
    }
    atomicAdd(&g_attn_applied[4 * t + 0], acc.x);
    atomicAdd(&g_attn_applied[4 * t + 1], acc.y);
    atomicAdd(&g_attn_applied[4 * t + 2], acc.z);
    atomicAdd(&g_attn_applied[4 * t + 3], acc.w);
}

// ---- 3. comb: 2 warps per row (split-K), 256 blocks x 4 rows ----
__global__ void __launch_bounds__(256) comb_kernel(
        const int* __restrict__ idx, const float* __restrict__ emb,
        const float* __restrict__ comb_W, const float* __restrict__ comb_b) {
    __shared__ float4 sin[512];
    __shared__ float spart[8];
    int t = threadIdx.x, warp = t >> 5, lane = t & 31;
    int row = idx[0];
    sin[t]       = ((const float4*)(emb + (size_t)row * H))[t];
    sin[256 + t] = ((const float4*)g_attn_applied)[t];
    __syncthreads();
    int r    = blockIdx.x * 4 + (warp >> 1);  // grid = 256 -> rows 0..1023
    int half = warp & 1;
    const float4* w = (const float4*)(comb_W + (size_t)r * (2 * H)) + half * 256;
    float acc = row_dot_1024(w, sin + half * 256, lane);
    acc = warp_sum(acc);
    if (lane == 0) spart[warp] = acc;
    __syncthreads();
    if (t < 4) {
        int rr = blockIdx.x * 4 + t;
        g_x[rr] = fmaxf(spart[2 * t] + spart[2 * t + 1] + comb_b[rr], 0.0f);
    }
}

// ---- 4. FUSED w_ih GEMV + LSTM: block b owns all 4 gates for j in {2b, 2b+1} ----
// warp w: gate g = w>>1, jj = w&1, row = g*H + 2b + jj. Then threads 0..1 do
// the elementwise LSTM for their j entirely in-block (g_ghh read from K1).
__global__ void __launch_bounds__(256) gates_lstm_kernel(
        const float* __restrict__ c0,
        const float* __restrict__ w_ih,
        const float* __restrict__ b_ih, const float* __restrict__ b_hh,
        float* __restrict__ out) {
    __shared__ float4 sx[256];
    __shared__ float sgate[8];                // [g*2 + jj]
    int t = threadIdx.x, warp = t >> 5, lane = t & 31;
    sx[t] = ((const float4*)g_x)[t];
    __syncthreads();
    int b = blockIdx.x;                       // grid = 512
    int g = warp >> 1, jj = warp & 1;
    int j = b * 2 + jj;
    size_t r = (size_t)g * H + j;
    const float4* w = (const float4*)(w_ih + r * H);
    float acc = row_dot_1024(w, sx, lane);
    acc = warp_sum(acc);
    if (lane == 0) sgate[warp] = acc + g_ghh[r] + b_ih[r] + b_hh[r];
    __syncthreads();
    if (t < 2) {
        int jo = b * 2 + t;
        float i_ = sigmoidf_(sgate[0 + t]);   // gate 0
        float f_ = sigmoidf_(sgate[2 + t]);   // gate 1
        float g_ = tanhf(sgate[4 + t]);       // gate 2
        float o_ = sigmoidf_(sgate[6 + t]);   // gate 3
        float c = f_ * c0[jo] + i_ * g_;
        float h = o_ * tanhf(c);
        g_h[jo] = h;
        out[OUT_H + jo] = h;
        out[OUT_C + jo] = c;
    }
}

// ---- 5. logits + fused block LSE: 4 rows per warp (32 LDG streams) ----
__global__ void __launch_bounds__(256) logits_kernel(
        const float* __restrict__ out_W, const float* __restrict__ out_b,
        float* __restrict__ out) {
    __shared__ float4 sh[256];
    __shared__ float s_m[8], s_s[8];
    int t = threadIdx.x, warp = t >> 5, lane = t & 31;
    sh[t] = ((const float4*)g_h)[t];
    __syncthreads();
    int r0 = blockIdx.x * LROWS + warp * 4;   // grid = NLOGB
    float m = -1e30f, s = 0.0f;
    if (r0 < VOCAB) {
        int nvalid = VOCAB - r0; if (nvalid > 4) nvalid = 4;
        const float4* w0 = (const float4*)(out_W + (size_t)r0 * H);
        const float4* w1 = (const float4*)(out_W + (size_t)(r0 + (nvalid > 1 ? 1 : 0)) * H);
        const float4* w2 = (const float4*)(out_W + (size_t)(r0 + (nvalid > 2 ? 2 : 0)) * H);
        const float4* w3 = (const float4*)(out_W + (size_t)(r0 + (nvalid > 3 ? 3 : 0)) * H);
        float a0 = 0.f, a1 = 0.f, a2 = 0.f, a3 = 0.f;
#pragma unroll
        for (int k = 0; k < 8; k++) {
            int i = lane + 32 * k;
            float4 hv = sh[i];
            a0 += dot4(hv, ldcs4(&w0[i]));
            a1 += dot4(hv, ldcs4(&w1[i]));
            a2 += dot4(hv, ldcs4(&w2[i]));
            a3 += dot4(hv, ldcs4(&w3[i]));
        }
        a0 = warp_sum(a0);
        a1 = warp_sum(a1);
        a2 = warp_sum(a2);
        a3 = warp_sum(a3);
        if (lane == 0) {
            float L[4] = {a0, a1, a2, a3};
            m = L[0] + out_b[r0];
            out[r0] = m;
            s = 1.0f;
#pragma unroll
            for (int q = 1; q < 4; q++) {
                if (q < nvalid) {
                    float Lq = L[q] + out_b[r0 + q];
                    out[r0 + q] = Lq;
                    if (Lq > m) { s = s * expf(m - Lq) + 1.0f; m = Lq; }
                    else        { s += expf(Lq - m); }
                }
            }
        }
    }
    if (lane == 0) { s_m[warp] = m; s_s[warp] = s; }
    __syncthreads();
    if (t == 0) {
        float M = s_m[0], S = s_s[0];
#pragma unroll
        for (int k = 1; k < 8; k++) {
            float m2 = s_m[k], s2 = s_s[k];
            float Mx = fmaxf(M, m2);
            S = S * expf(M - Mx) + s2 * expf(m2 - Mx);
            M = Mx;
        }
        g_pmax[blockIdx.x] = M;
        g_psum[blockIdx.x] = S;
    }
}

// ---- 6. final LSE combine (redundant per block) + subtract ----
__global__ void __launch_bounds__(256) sub_lse_kernel(float* __restrict__ out) {
    __shared__ float rm[256], rs[256];
    int t = threadIdx.x;
    float m = -1e30f, s = 0.0f;
    for (int i = t; i < NLOGB; i += 256) {
        float m2 = g_pmax[i], s2 = g_psum[i];
        float M = fmaxf(m, m2);
        s = s * expf(m - M) + s2 * expf(m2 - M);
        m = M;
    }
    rm[t] = m; rs[t] = s;
    __syncthreads();
    for (int k = 128; k > 0; k >>= 1) {
        if (t < k) {
            float m2 = rm[t + k], s2 = rs[t + k];
            float M = fmaxf(rm[t], m2);
            rs[t] = rs[t] * expf(rm[t] - M) + s2 * expf(m2 - M);
            rm[t] = M;
        }
        __syncthreads();
    }
    float lse = rm[0] + logf(rs[0]);
    int base = blockIdx.x * 1024;             // grid = 50
#pragma unroll
    for (int k = 0; k < 4; k++) {
        int i = base + t + 256 * k;
        if (i < VOCAB) out[i] -= lse;
    }
}

extern "C" void kernel_launch(void* const* d_in, const int* in_sizes, int n_in,
                              void* d_out, int out_size) {
    const int*   idx     = (const int*)  d_in[0];
    const float* h0      = (const float*)d_in[1];
    const float* c0      = (const float*)d_in[2];
    const float* enc     = (const float*)d_in[3];
    const float* emb     = (const float*)d_in[4];
    const float* attn_W  = (const float*)d_in[5];
    const float* attn_b  = (const float*)d_in[6];
    const float* comb_W  = (const float*)d_in[7];
    const float* comb_b  = (const float*)d_in[8];
    const float* w_ih    = (const float*)d_in[9];
    const float* w_hh    = (const float*)d_in[10];
    const float* b_ih    = (const float*)d_in[11];
    const float* b_hh    = (const float*)d_in[12];
    const float* out_W   = (const float*)d_in[13];
    const float* out_b   = (const float*)d_in[14];
    float* out = (float*)d_out;

    attn_whh_kernel<<<128 + 512, 256>>>(idx, emb, h0, attn_W, attn_b, w_hh);
    attn_applied_kernel<<<64, 256>>>(enc, out);
    comb_kernel<<<H / 4, 256>>>(idx, emb, comb_W, comb_b);
    gates_lstm_kernel<<<512, 256>>>(c0, w_ih, b_ih, b_hh, out);
    logits_kernel<<<NLOGB, 256>>>(out_W, out_b, out);
    sub_lse_kernel<<<(VOCAB + 1023) / 1024, 256>>>(out);
}